// round 15
// baseline (speedup 1.0000x reference)
#include <cuda_runtime.h>
#include <cstdint>

// Problem constants (fixed by reference)
#define NB    8
#define HH    512
#define WW    512
#define DD    8
#define HWC   (HH * WW)          // 262144
#define NPIX  (NB * HWC)         // 2097152 = 2^21
#define TPB   128
#define NSM   148
#define BPSM  7                  // 7 blocks/SM = 28 warps; 73-reg budget
#define GRID  (NSM * BPSM)       // 1036 = exactly ONE full wave (persistent)
#define TOTAL (GRID * TPB)       // 132608 threads
#define MAXJ  ((NPIX + TOTAL - 1) / TOTAL)   // 16 (last stage partial)

// 256-bit gather load with L2 evict_last (sm_103 requires v8.b32 for this hint).
__device__ __forceinline__ void ldg256_el(const void* p, float4& a, float4& b) {
    asm volatile(
        "ld.global.nc.L2::evict_last.v8.b32 {%0,%1,%2,%3,%4,%5,%6,%7}, [%8];"
        : "=r"(*(unsigned*)&a.x), "=r"(*(unsigned*)&a.y),
          "=r"(*(unsigned*)&a.z), "=r"(*(unsigned*)&a.w),
          "=r"(*(unsigned*)&b.x), "=r"(*(unsigned*)&b.y),
          "=r"(*(unsigned*)&b.z), "=r"(*(unsigned*)&b.w)
        : "l"(p));
}

__global__ __launch_bounds__(TPB, BPSM)
void interp_kernel(const void* __restrict__ p2f_raw,
                   const float* __restrict__ bary,     // [NPIX,3]
                   const float* __restrict__ attr,     // [N*NF][3][8] fp32 = 96 B/face
                   float* __restrict__ out)            // [N][9][H][W]
{
    const int t = blockIdx.x * TPB + threadIdx.x;      // t < 132608

    // ---- dtype detection (int64 vs int32 pix_to_face), warp-uniform ----
    // t < NPIX/2, so word index 2t+1 is in-bounds under BOTH interpretations.
    // int64: hi word of every element is 0 or 0xFFFFFFFF -> 32/32 lanes match.
    // int32: sampled words are arbitrary face values -> ~6-7/32 match.
    const unsigned int* pw = (const unsigned int*)p2f_raw;
    unsigned int hiw = __ldg(&pw[2 * t + 1]);
    bool m = (hiw == 0u) || (hiw == 0xFFFFFFFFu);
    const bool is64 = __popc(__ballot_sync(0xffffffffu, m)) >= 28;

    // Pipeline state (register-lean):
    //   face idx: 3 slots (gather address chain needs lookahead 2)
    //   bary:     2 slots (lookahead 1; coalesced stream hides in one stage)
    //   attr:     2 buffers (lookahead 1)
    int    fq[3];
    float  bq[2][3];
    float4 A[2][6];

    auto load_face = [&](int s, int j) {
        int pix = t + j * TOTAL;
        if (pix < NPIX) {
            if (is64) fq[s] = (int)__ldcs((const long long*)p2f_raw + pix);
            else      fq[s] = __ldcs((const int*)p2f_raw + pix);
        } else {
            fq[s] = -1;                       // makes load_attr/compute skip
        }
    };
    auto load_bary = [&](int s, int j) {
        int pix = t + j * TOTAL;
        if (pix < NPIX) {
            const float* bp = bary + (size_t)pix * 3;
            bq[s][0] = __ldcs(bp + 0);
            bq[s][1] = __ldcs(bp + 1);
            bq[s][2] = __ldcs(bp + 2);
        }
    };
    // issue 3 x LDG.256 gather (96 B face payload) for slot s into buffer buf
    auto load_attr = [&](int buf, int s) {
        int f = fq[s];
        if (f >= 0) {
            const float* a = attr + (size_t)f * 24;
            ldg256_el(a + 0,  A[buf][0], A[buf][1]);   // vertex 0: ch 0-7
            ldg256_el(a + 8,  A[buf][2], A[buf][3]);   // vertex 1
            ldg256_el(a + 16, A[buf][4], A[buf][5]);   // vertex 2
        }
    };

    // ---- prologue: fill the pipe ----
    load_face(0, 0);
    load_face(1, 1);
    load_bary(0, 0);
    load_attr(0, 0);

    #pragma unroll
    for (int j = 0; j < MAXJ; j++) {
        if (j + 2 < MAXJ) load_face((j + 2) % 3, j + 2);
        if (j + 1 < MAXJ) {
            load_bary((j + 1) & 1, j + 1);
            load_attr((j + 1) & 1, (j + 1) % 3);
        }

        // ---- compute + store stage j (fused: no output buffer array) ----
        int pix = t + j * TOTAL;
        if (pix >= NPIX) break;               // only possible at j == MAXJ-1

        const int buf = j & 1;
        const int f   = fq[j % 3];
        int n  = pix >> 18;                   // / HWC (2^18)
        int hw = pix & (HWC - 1);
        float* ob = out + (size_t)n * (DD + 1) * HWC + hw;

        if (f >= 0) {
            float b0 = bq[buf][0], b1 = bq[buf][1], b2 = bq[buf][2];
            float4 A0 = A[buf][0], A1 = A[buf][1];
            float4 A2 = A[buf][2], A3 = A[buf][3];
            float4 A4 = A[buf][4], A5 = A[buf][5];
            __stcs(ob + 0 * (size_t)HWC, b0 * A0.x + b1 * A2.x + b2 * A4.x);
            __stcs(ob + 1 * (size_t)HWC, b0 * A0.y + b1 * A2.y + b2 * A4.y);
            __stcs(ob + 2 * (size_t)HWC, b0 * A0.z + b1 * A2.z + b2 * A4.z);
            __stcs(ob + 3 * (size_t)HWC, b0 * A0.w + b1 * A2.w + b2 * A4.w);
            __stcs(ob + 4 * (size_t)HWC, b0 * A1.x + b1 * A3.x + b2 * A5.x);
            __stcs(ob + 5 * (size_t)HWC, b0 * A1.y + b1 * A3.y + b2 * A5.y);
            __stcs(ob + 6 * (size_t)HWC, b0 * A1.z + b1 * A3.z + b2 * A5.z);
            __stcs(ob + 7 * (size_t)HWC, b0 * A1.w + b1 * A3.w + b2 * A5.w);
            __stcs(ob + 8 * (size_t)HWC, 1.0f);
        } else {
            #pragma unroll
            for (int d = 0; d <= DD; d++)
                __stcs(ob + (size_t)d * HWC, 0.0f);
        }
    }
}

extern "C" void kernel_launch(void* const* d_in, const int* in_sizes, int n_in,
                              void* d_out, int out_size) {
    const void*  p2f  = d_in[0];                    // [N,H,W,1] int32 or int64
    const float* bary = (const float*)d_in[1];      // [N,H,W,1,3] fp32
    const float* attr = (const float*)d_in[2];      // [N,NF,3,8] fp32
    float*       out  = (float*)d_out;              // [N,9,H,W] fp32

    interp_kernel<<<GRID, TPB>>>(p2f, bary, attr, out);
}

// round 16
// speedup vs baseline: 1.1222x; 1.1222x over previous
#include <cuda_runtime.h>
#include <cstdint>

// Problem constants (fixed by reference)
#define NB    8
#define HH    512
#define WW    512
#define DD    8
#define HWC   (HH * WW)          // 262144
#define NPIX  (NB * HWC)         // 2097152 = 2^21
#define TPB   128
#define NSM   148
#define BPSM  6                  // 6 blocks/SM: the no-spill optimum (80 regs natural)
#define GRID  (NSM * BPSM)       // 888 = exactly ONE full wave (persistent)
#define TOTAL (GRID * TPB)       // 113664 threads
#define MAXJ  ((NPIX + TOTAL - 1) / TOTAL)   // 19 (last stage partial)

// 256-bit gather load with L2 evict_last (sm_103 requires v8.b32 for this hint).
__device__ __forceinline__ void ldg256_el(const void* p, float4& a, float4& b) {
    asm volatile(
        "ld.global.nc.L2::evict_last.v8.b32 {%0,%1,%2,%3,%4,%5,%6,%7}, [%8];"
        : "=r"(*(unsigned*)&a.x), "=r"(*(unsigned*)&a.y),
          "=r"(*(unsigned*)&a.z), "=r"(*(unsigned*)&a.w),
          "=r"(*(unsigned*)&b.x), "=r"(*(unsigned*)&b.y),
          "=r"(*(unsigned*)&b.z), "=r"(*(unsigned*)&b.w)
        : "l"(p));
}

__global__ __launch_bounds__(TPB, BPSM)
void interp_kernel(const void* __restrict__ p2f_raw,
                   const float* __restrict__ bary,     // [NPIX,3]
                   const float* __restrict__ attr,     // [N*NF][3][8] fp32 = 96 B/face
                   float* __restrict__ out)            // [N][9][H][W]
{
    const int t = blockIdx.x * TPB + threadIdx.x;      // t < 113664

    // ---- dtype detection (int64 vs int32 pix_to_face), warp-uniform ----
    // t < NPIX/2, so word index 2t+1 is in-bounds under BOTH interpretations.
    // int64: hi word of every element is 0 or 0xFFFFFFFF -> 32/32 lanes match.
    // int32: sampled words are arbitrary face values -> ~6-7/32 match.
    const unsigned int* pw = (const unsigned int*)p2f_raw;
    unsigned int hiw = __ldg(&pw[2 * t + 1]);
    bool m = (hiw == 0u) || (hiw == 0xFFFFFFFFu);
    const bool is64 = __popc(__ballot_sync(0xffffffffu, m)) >= 28;

    // Pipeline state: 3 idx/bary slots, 2 attr buffers.
    int    fq[3];
    float  bq[3][3];
    float4 A[2][6];

    // issue face index + barycentrics for stage j into slot s (single-use -> streaming)
    auto load_idx = [&](int s, int j) {
        int pix = t + j * TOTAL;
        if (pix < NPIX) {
            if (is64) fq[s] = (int)__ldcs((const long long*)p2f_raw + pix);
            else      fq[s] = __ldcs((const int*)p2f_raw + pix);
            const float* bp = bary + (size_t)pix * 3;
            bq[s][0] = __ldcs(bp + 0);
            bq[s][1] = __ldcs(bp + 1);
            bq[s][2] = __ldcs(bp + 2);
        } else {
            fq[s] = -1;                       // makes load_attr/compute skip
        }
    };

    // issue 3 x LDG.256 gather (96 B face payload) for slot s into buffer buf
    auto load_attr = [&](int buf, int s) {
        int f = fq[s];
        if (f >= 0) {
            const float* a = attr + (size_t)f * 24;
            ldg256_el(a + 0,  A[buf][0], A[buf][1]);   // vertex 0: ch 0-7
            ldg256_el(a + 8,  A[buf][2], A[buf][3]);   // vertex 1
            ldg256_el(a + 16, A[buf][4], A[buf][5]);   // vertex 2
        }
    };

    // ---- prologue: fill the pipe ----
    load_idx(0, 0);
    load_idx(1, 1);
    load_attr(0, 0);

    #pragma unroll
    for (int j = 0; j < MAXJ; j++) {
        if (j + 2 < MAXJ) load_idx((j + 2) % 3, j + 2);
        if (j + 1 < MAXJ) load_attr((j + 1) & 1, (j + 1) % 3);

        // ---- compute + store stage j ----
        int pix = t + j * TOTAL;
        if (pix >= NPIX) break;               // only possible at j == MAXJ-1

        const int s   = j % 3;
        const int buf = j & 1;
        const int f   = fq[s];
        float o[DD], vis;
        if (f >= 0) {
            float b0 = bq[s][0], b1 = bq[s][1], b2 = bq[s][2];
            float4 A0 = A[buf][0], A1 = A[buf][1];
            float4 A2 = A[buf][2], A3 = A[buf][3];
            float4 A4 = A[buf][4], A5 = A[buf][5];
            o[0] = b0 * A0.x + b1 * A2.x + b2 * A4.x;
            o[1] = b0 * A0.y + b1 * A2.y + b2 * A4.y;
            o[2] = b0 * A0.z + b1 * A2.z + b2 * A4.z;
            o[3] = b0 * A0.w + b1 * A2.w + b2 * A4.w;
            o[4] = b0 * A1.x + b1 * A3.x + b2 * A5.x;
            o[5] = b0 * A1.y + b1 * A3.y + b2 * A5.y;
            o[6] = b0 * A1.z + b1 * A3.z + b2 * A5.z;
            o[7] = b0 * A1.w + b1 * A3.w + b2 * A5.w;
            vis = 1.0f;
        } else {
            #pragma unroll
            for (int d = 0; d < DD; d++) o[d] = 0.0f;
            vis = 0.0f;
        }

        // output [N][9][H][W]: warp-coalesced plane-major stores, streaming
        int n  = pix >> 18;             // / HWC (2^18)
        int hw = pix & (HWC - 1);
        float* ob = out + (size_t)n * (DD + 1) * HWC + hw;
        #pragma unroll
        for (int d = 0; d < DD; d++)
            __stcs(ob + (size_t)d * HWC, o[d]);
        __stcs(ob + (size_t)DD * HWC, vis);
    }
}

extern "C" void kernel_launch(void* const* d_in, const int* in_sizes, int n_in,
                              void* d_out, int out_size) {
    const void*  p2f  = d_in[0];                    // [N,H,W,1] int32 or int64
    const float* bary = (const float*)d_in[1];      // [N,H,W,1,3] fp32
    const float* attr = (const float*)d_in[2];      // [N,NF,3,8] fp32
    float*       out  = (float*)d_out;              // [N,9,H,W] fp32

    interp_kernel<<<GRID, TPB>>>(p2f, bary, attr, out);
}